// round 12
// baseline (speedup 1.0000x reference)
#include <cuda_runtime.h>

// DendriticLayer: B=512, N_IN=1024, N_OUT=256, T=100, dt=1.
// Event-scatter recurrence (R9) + time-split x2 (R12):
//   thread p=0 handles t in [0,52), p=1 handles t in [52,100) (+4 masked pad).
//   p=1 initializes (C,w) at t=51 in CLOSED FORM from its 4 events:
//     C51 = sum c_j d^n,  w51 = sum c_j (A d^n - B 0.9^n),  n = 51-e_j >= 0
//     A = d/(d-0.9), B = 0.9/(d-0.9)
//   Both parities run an identical 13-chunk body (no divergence); p1's last
//   chunk (t=100..103) goes to separate accumulators and is dropped.
//   WS uses local-time immediates; epilogue adds base*S (base = 52p).

#define NCH 13

__device__ __forceinline__ float ex2(float x) {
    float y;
    asm("ex2.approx.ftz.f32 %0, %1;" : "=f"(y) : "f"(x));
    return y;
}

constexpr double Dd  = 0.81873075307798185867;   // exp(-0.2)
constexpr float  D1f = (float)Dd;
constexpr float  K2f = 2.8853900817779268147f;   // 2*log2(e)
constexpr float  L2D = -0.28853900817779268f;    // log2(d)
constexpr float  L2N = -0.15200309344504995f;    // log2(0.9)
constexpr float  Af  = (float)(Dd / (Dd - 0.9));        // ~ -10.0743
constexpr float  NBf = (float)(-0.9 / (Dd - 0.9));      // ~ +11.0743 (= -B)

struct Acc { float C, w, S, WS, Sa, Wa; };

template <bool LAST>
__device__ __forceinline__ void step(Acc& a, float dlt, float tf) {
    a.C = fmaf(a.C, D1f, dlt);
    a.w = fmaf(a.w, 0.9f, a.C);
    const float e = ex2(a.w);
    if constexpr (LAST) { a.Sa += e; a.Wa = fmaf(e, tf, a.Wa); }
    else                { a.S  += e; a.WS = fmaf(e, tf, a.WS); }
}

template <int K>
__device__ __forceinline__ void run(Acc& a, const float4* __restrict__ col) {
    if constexpr (K < NCH) {
        const float4 d4 = col[K * 128];          // LDS.128 (R9 pattern)
        constexpr bool LAST = (K == NCH - 1);    // p1 drops this chunk
        step<LAST>(a, d4.x, (float)(4 * K + 0)); // local-time immediates
        step<LAST>(a, d4.y, (float)(4 * K + 1));
        step<LAST>(a, d4.z, (float)(4 * K + 2));
        step<LAST>(a, d4.w, (float)(4 * K + 3));
        run<K + 1>(a, col);
    }
}

__global__ __launch_bounds__(128)
void dendritic_kernel(const float* __restrict__ spikes,  // [512,1024]
                      const float* __restrict__ W,       // [256,1024]
                      float* __restrict__ out)           // [512,256]
{
    __shared__ float4 tbl[NCH][128];                     // 26.6KB

    const int tid  = threadIdx.x;
    const int gid  = blockIdx.x * 128 + tid;
    const int lane = tid & 31;
    const int p    = lane >> 4;                          // time-half parity
    const int elem = ((gid >> 5) << 4) + (lane & 15);    // b*256 + o
    const int o    = elem & 255;

    // lanes 0-15 load 16 consecutive float4s; lanes 16-31 replay (L1 hit)
    const float4 s4 = reinterpret_cast<const float4*>(spikes)[elem];
    const float4 w4 = reinterpret_cast<const float4*>(W)[257 * o];

    const float e0 = ceilf(s4.x), e1 = ceilf(s4.y), e2 = ceilf(s4.z), e3 = ceilf(s4.w);
    const float kk = 0.1f * K2f;
    const float c0 = kk * w4.x * __expf(0.2f * (s4.x - e0));
    const float c1 = kk * w4.y * __expf(0.2f * (s4.y - e1));
    const float c2 = kk * w4.z * __expf(0.2f * (s4.z - e2));
    const float c3 = kk * w4.w * __expf(0.2f * (s4.w - e3));

    // ---- zero + scatter this thread's time window ----
    float* tf4 = reinterpret_cast<float*>(tbl);
    const int tb = tid * 4;
    #define SLOT(k) (((k) >> 2) * 512 + tb + ((k) & 3))

    #pragma unroll
    for (int c = 0; c < NCH; ++c) tbl[c][tid] = make_float4(0.f, 0.f, 0.f, 0.f);

    const int base = p ? 52 : 0;
    const int k0 = (int)e0 - base, k1 = (int)e1 - base,
              k2 = (int)e2 - base, k3 = (int)e3 - base;
    if ((unsigned)k0 < 52u) tf4[SLOT(k0)] += c0;   // thread-private column
    if ((unsigned)k1 < 52u) tf4[SLOT(k1)] += c1;
    if ((unsigned)k2 < 52u) tf4[SLOT(k2)] += c2;
    if ((unsigned)k3 < 52u) tf4[SLOT(k3)] += c3;

    // ---- p=1: closed-form state at t=51 ----
    Acc a; a.C = 0.f; a.w = 0.f; a.S = 0.f; a.WS = 0.f; a.Sa = 0.f; a.Wa = 0.f;
    if (p) {
        float n, dp, np;
        n = 51.0f - e0;
        if (n >= 0.f) { dp = ex2(n * L2D); np = ex2(n * L2N);
            a.C = fmaf(c0, dp, a.C); a.w = fmaf(c0, fmaf(Af, dp, NBf * np), a.w); }
        n = 51.0f - e1;
        if (n >= 0.f) { dp = ex2(n * L2D); np = ex2(n * L2N);
            a.C = fmaf(c1, dp, a.C); a.w = fmaf(c1, fmaf(Af, dp, NBf * np), a.w); }
        n = 51.0f - e2;
        if (n >= 0.f) { dp = ex2(n * L2D); np = ex2(n * L2N);
            a.C = fmaf(c2, dp, a.C); a.w = fmaf(c2, fmaf(Af, dp, NBf * np), a.w); }
        n = 51.0f - e3;
        if (n >= 0.f) { dp = ex2(n * L2D); np = ex2(n * L2N);
            a.C = fmaf(c3, dp, a.C); a.w = fmaf(c3, fmaf(Af, dp, NBf * np), a.w); }
    }

    // ---- identical 13-chunk body for both parities ----
    run<0>(a, &tbl[0][tid]);

    // p0 keeps last chunk (t=48..51); p1 drops it (t=100..103 padding)
    const float keep = p ? 0.0f : 1.0f;
    const float Sown = fmaf(keep, a.Sa, a.S);
    float       Wown = fmaf(keep, a.Wa, a.WS);
    Wown = fmaf((float)base, Sown, Wown);          // local->global time

    const float Sot = __shfl_xor_sync(0xffffffffu, Sown, 16);
    const float Wot = __shfl_xor_sync(0xffffffffu, Wown, 16);
    if (p == 0) out[elem] = (Wown + Wot) / (Sown + Sot);
}

extern "C" void kernel_launch(void* const* d_in, const int* in_sizes, int n_in,
                              void* d_out, int out_size)
{
    const float* spikes = (const float*)d_in[0];  // [512*1024]
    const float* W      = (const float*)d_in[1];  // [256*1024]
    float* out          = (float*)d_out;          // [512*256]

    // 131072 elements x 2 time-halves = 262144 threads = 2048 blocks x 128
    dendritic_kernel<<<2048, 128>>>(spikes, W, out);
}

// round 13
// speedup vs baseline: 1.0152x; 1.0152x over previous
#include <cuda_runtime.h>

// DendriticLayer: B=512, N_IN=1024, N_OUT=256, T=100, dt=1.
// Event-scatter recurrence + time-split x2 (R12) + single-wave SMEM (R13):
//   2 threads per element: p=0 -> t in [0,52), p=1 -> t in [52,100)+4 pad.
//   p=1 state at t=51 in closed form (validated in R12):
//     C51 = sum c_j d^n,  w51 = sum c_j (A d^n - B 0.9^n),  n = 51-e_j >= 0
//   Each thread runs TWO sub-phases (28 + 24 steps) over a 7-chunk table
//   -> 14.3KB/block -> 15 blocks/SM resident -> 2048-block grid in ONE wave
//   (55 warps/SM, 2x R9). Identical instruction stream for both parities.

#define CHA 7   // sub-phase A: 28 steps
#define CHB 6   // sub-phase B: 24 steps (last chunk = pad for p1, masked)

__device__ __forceinline__ float ex2(float x) {
    float y;
    asm("ex2.approx.ftz.f32 %0, %1;" : "=f"(y) : "f"(x));
    return y;
}

constexpr double Dd  = 0.81873075307798185867;   // exp(-0.2)
constexpr float  D1f = (float)Dd;
constexpr float  K2f = 2.8853900817779268147f;   // 2*log2(e)
constexpr float  L2D = -0.28853900817779268f;    // log2(d)
constexpr float  L2N = -0.15200309344504995f;    // log2(0.9)
constexpr float  Af  = (float)(Dd / (Dd - 0.9));     // ~ -10.0743
constexpr float  NBf = (float)(-0.9 / (Dd - 0.9));   // ~ +11.0743 (= -B)

struct Acc { float C, w, S, WS, Sa, Wa; };

template <bool LAST>
__device__ __forceinline__ void step(Acc& a, float dlt, float tf) {
    a.C = fmaf(a.C, D1f, dlt);
    a.w = fmaf(a.w, 0.9f, a.C);
    const float e = ex2(a.w);
    if constexpr (LAST) { a.Sa += e; a.Wa = fmaf(e, tf, a.Wa); }
    else                { a.S  += e; a.WS = fmaf(e, tf, a.WS); }
}

template <int T0, int NCH, int K, bool MASK_LAST>
__device__ __forceinline__ void run(Acc& a, const float4* __restrict__ col) {
    if constexpr (K < NCH) {
        const float4 d4 = col[K * 128];                  // LDS.128
        constexpr bool L = MASK_LAST && (K == NCH - 1);  // pad chunk (p1)
        step<L>(a, d4.x, (float)(T0 + 4 * K + 0));       // local-time imm
        step<L>(a, d4.y, (float)(T0 + 4 * K + 1));
        step<L>(a, d4.z, (float)(T0 + 4 * K + 2));
        step<L>(a, d4.w, (float)(T0 + 4 * K + 3));
        run<T0, NCH, K + 1, MASK_LAST>(a, col);
    }
}

__global__ __launch_bounds__(128, 14)
void dendritic_kernel(const float* __restrict__ spikes,  // [512,1024]
                      const float* __restrict__ W,       // [256,1024]
                      float* __restrict__ out)           // [512,256]
{
    __shared__ float4 tbl[CHA][128];                     // 14.3KB

    const int tid  = threadIdx.x;
    const int gid  = blockIdx.x * 128 + tid;
    const int lane = tid & 31;
    const int p    = lane >> 4;                          // time-half parity
    const int elem = ((gid >> 5) << 4) + (lane & 15);    // b*256 + o
    const int o    = elem & 255;

    const float4 s4 = reinterpret_cast<const float4*>(spikes)[elem];
    const float4 w4 = reinterpret_cast<const float4*>(W)[257 * o];

    const float e0 = ceilf(s4.x), e1 = ceilf(s4.y), e2 = ceilf(s4.z), e3 = ceilf(s4.w);
    const float kk = 0.1f * K2f;
    const float c0 = kk * w4.x * __expf(0.2f * (s4.x - e0));
    const float c1 = kk * w4.y * __expf(0.2f * (s4.y - e1));
    const float c2 = kk * w4.z * __expf(0.2f * (s4.z - e2));
    const float c3 = kk * w4.w * __expf(0.2f * (s4.w - e3));

    float* tf4 = reinterpret_cast<float*>(tbl);
    const int tb = tid * 4;
    #define SLOT(k) (((k) >> 2) * 512 + tb + ((k) & 3))

    const int base = p ? 52 : 0;
    const int k0 = (int)e0 - base, k1 = (int)e1 - base,
              k2 = (int)e2 - base, k3 = (int)e3 - base;

    // ---- p=1: closed-form state at t=51 (one-time half-warp divergence) ----
    Acc a; a.C = 0.f; a.w = 0.f; a.S = 0.f; a.WS = 0.f; a.Sa = 0.f; a.Wa = 0.f;
    if (p) {
        float n, dp, np;
        n = 51.0f - e0;
        if (n >= 0.f) { dp = ex2(n * L2D); np = ex2(n * L2N);
            a.C = fmaf(c0, dp, a.C); a.w = fmaf(c0, fmaf(Af, dp, NBf * np), a.w); }
        n = 51.0f - e1;
        if (n >= 0.f) { dp = ex2(n * L2D); np = ex2(n * L2N);
            a.C = fmaf(c1, dp, a.C); a.w = fmaf(c1, fmaf(Af, dp, NBf * np), a.w); }
        n = 51.0f - e2;
        if (n >= 0.f) { dp = ex2(n * L2D); np = ex2(n * L2N);
            a.C = fmaf(c2, dp, a.C); a.w = fmaf(c2, fmaf(Af, dp, NBf * np), a.w); }
        n = 51.0f - e3;
        if (n >= 0.f) { dp = ex2(n * L2D); np = ex2(n * L2N);
            a.C = fmaf(c3, dp, a.C); a.w = fmaf(c3, fmaf(Af, dp, NBf * np), a.w); }
    }

    // ---- sub-phase A: local k in [0,28) ----
    #pragma unroll
    for (int c = 0; c < CHA; ++c) tbl[c][tid] = make_float4(0.f, 0.f, 0.f, 0.f);
    if ((unsigned)k0 < 28u) tf4[SLOT(k0)] += c0;   // thread-private column
    if ((unsigned)k1 < 28u) tf4[SLOT(k1)] += c1;
    if ((unsigned)k2 < 28u) tf4[SLOT(k2)] += c2;
    if ((unsigned)k3 < 28u) tf4[SLOT(k3)] += c3;
    run<0, CHA, 0, false>(a, &tbl[0][tid]);

    // ---- sub-phase B: local k in [28,52); last chunk is pad for p1 ----
    #pragma unroll
    for (int c = 0; c < CHB; ++c) tbl[c][tid] = make_float4(0.f, 0.f, 0.f, 0.f);
    {
        const int m0 = k0 - 28, m1 = k1 - 28, m2 = k2 - 28, m3 = k3 - 28;
        if ((unsigned)m0 < 24u) tf4[SLOT(m0)] += c0;
        if ((unsigned)m1 < 24u) tf4[SLOT(m1)] += c1;
        if ((unsigned)m2 < 24u) tf4[SLOT(m2)] += c2;
        if ((unsigned)m3 < 24u) tf4[SLOT(m3)] += c3;
    }
    run<28, CHB, 0, true>(a, &tbl[0][tid]);

    // p0 keeps the last chunk (local t=44..47 -> real); p1 drops pad (t>=100)
    const float keep = p ? 0.0f : 1.0f;
    const float Sown = fmaf(keep, a.Sa, a.S);
    float       Wown = fmaf(keep, a.Wa, a.WS);
    Wown = fmaf((float)base, Sown, Wown);          // local -> global time

    const float Sot = __shfl_xor_sync(0xffffffffu, Sown, 16);
    const float Wot = __shfl_xor_sync(0xffffffffu, Wown, 16);
    if (p == 0) out[elem] = (Wown + Wot) / (Sown + Sot);
}

extern "C" void kernel_launch(void* const* d_in, const int* in_sizes, int n_in,
                              void* d_out, int out_size)
{
    const float* spikes = (const float*)d_in[0];  // [512*1024]
    const float* W      = (const float*)d_in[1];  // [256*1024]
    float* out          = (float*)d_out;          // [512*256]

    // 131072 elements x 2 time-halves = 262144 threads = 2048 blocks x 128
    dendritic_kernel<<<2048, 128>>>(spikes, W, out);
}

// round 15
// speedup vs baseline: 1.1964x; 1.1786x over previous
#include <cuda_runtime.h>

// DendriticLayer: B=512, N_IN=1024, N_OUT=256, T=100, dt=1.
// Event-scatter formulation (R9 = best):
//   delta[ceil(s_j)] += 0.1*K2*w_j*exp((s_j-ceil(s_j))/5)   (private SMEM col)
//   Chat_t = d*Chat_{t-1} + delta_t ;  w_t = 0.9*w_{t-1} + Chat_t  (w = K2*v)
//   e_t = exp2(w_t);  out = (sum t*e_t)/(sum e_t)
// R15 = R9 with ONE change: phase-1 re-zero (12x STS.128) replaced by
// targeted zeroing of the <=4 slots this thread dirtied in phase 0
// (guarded scalar STS). Cuts total smem wavefronts ~22%.

#define CH0 13   // phase-0: 52 steps (t in [0,52))
#define CH1 12   // phase-1: 48 steps (t in [52,100))

__device__ __forceinline__ float ex2(float x) {
    float y;
    asm("ex2.approx.ftz.f32 %0, %1;" : "=f"(y) : "f"(x));
    return y;
}

constexpr float D1f = 0.81873075307798185867f;  // exp(-0.2)
constexpr float K2f = 2.8853900817779268147f;   // 2*log2(e)

struct Acc { float C, w, S, WS; };

__device__ __forceinline__ void step(Acc& a, float dlt, float tf) {
    a.C = fmaf(a.C, D1f, dlt);    // FFMA-imm
    a.w = fmaf(a.w, 0.9f, a.C);   // FFMA-imm
    const float e = ex2(a.w);     // MUFU.EX2
    a.S += e;                     // FADD
    a.WS = fmaf(e, tf, a.WS);     // FFMA-imm
}

template <int T0, int NCH, int K>
__device__ __forceinline__ void run(Acc& a, const float4* __restrict__ col) {
    if constexpr (K < NCH) {
        const float4 d4 = col[K * 128];          // LDS.128: 4 steps of deltas
        step(a, d4.x, (float)(T0 + 4 * K + 0));
        step(a, d4.y, (float)(T0 + 4 * K + 1));
        step(a, d4.z, (float)(T0 + 4 * K + 2));
        step(a, d4.w, (float)(T0 + 4 * K + 3));
        run<T0, NCH, K + 1>(a, col);
    }
}

__global__ __launch_bounds__(128)
void dendritic_kernel(const float* __restrict__ spikes,  // [512,1024]
                      const float* __restrict__ W,       // [256,1024]
                      float* __restrict__ out)           // [512,256]
{
    __shared__ float4 tbl[CH0][128];             // 26.6KB

    const int tid = threadIdx.x;
    const int idx = blockIdx.x * 128 + tid;      // b*256 + o
    const int o   = idx & 255;

    const float4 s4 = reinterpret_cast<const float4*>(spikes)[idx];
    const float4 w4 = reinterpret_cast<const float4*>(W)[257 * o];

    const float e0 = ceilf(s4.x), e1 = ceilf(s4.y), e2 = ceilf(s4.z), e3 = ceilf(s4.w);
    const float kk = 0.1f * K2f;
    const float c0 = kk * w4.x * __expf(0.2f * (s4.x - e0));
    const float c1 = kk * w4.y * __expf(0.2f * (s4.y - e1));
    const float c2 = kk * w4.z * __expf(0.2f * (s4.z - e2));
    const float c3 = kk * w4.w * __expf(0.2f * (s4.w - e3));
    const int i0 = (int)e0, i1 = (int)e1, i2 = (int)e2, i3 = (int)e3;

    float* tf = reinterpret_cast<float*>(tbl);
    const int tb = tid * 4;
    // scalar slot for timestep k (local to a phase): (k>>2)*512 + tid*4 + (k&3)
    #define SLOT(k) (((k) >> 2) * 512 + tb + ((k) & 3))

    const float4* col = &tbl[0][tid];
    float4 z4 = make_float4(0.f, 0.f, 0.f, 0.f);
    Acc a; a.C = 0.f; a.w = 0.f; a.S = 0.f; a.WS = 0.f;

    // ---- phase 0: t in [0,52) ----
    #pragma unroll
    for (int c = 0; c < CH0; ++c) tbl[c][tid] = z4;       // 13x STS.128 (only full zero)
    if (i0 < 52) tf[SLOT(i0)] += c0;                       // private RMW, race-free
    if (i1 < 52) tf[SLOT(i1)] += c1;
    if (i2 < 52) tf[SLOT(i2)] += c2;
    if (i3 < 52) tf[SLOT(i3)] += c3;
    run<0, CH0, 0>(a, col);

    // ---- targeted clean: zero only the slots we dirtied (<=4 scalar STS) ----
    if (i0 < 52) tf[SLOT(i0)] = 0.0f;
    if (i1 < 52) tf[SLOT(i1)] = 0.0f;
    if (i2 < 52) tf[SLOT(i2)] = 0.0f;
    if (i3 < 52) tf[SLOT(i3)] = 0.0f;

    // ---- phase 1: t in [52,100); chunks 0..11 are now clean ----
    const int j0 = i0 - 52, j1 = i1 - 52, j2 = i2 - 52, j3 = i3 - 52;
    if ((unsigned)j0 < 48u) tf[SLOT(j0)] += c0;
    if ((unsigned)j1 < 48u) tf[SLOT(j1)] += c1;
    if ((unsigned)j2 < 48u) tf[SLOT(j2)] += c2;
    if ((unsigned)j3 < 48u) tf[SLOT(j3)] += c3;
    run<52, CH1, 0>(a, col);

    out[idx] = a.WS / a.S;
}

extern "C" void kernel_launch(void* const* d_in, const int* in_sizes, int n_in,
                              void* d_out, int out_size)
{
    const float* spikes = (const float*)d_in[0];  // [512*1024]
    const float* W      = (const float*)d_in[1];  // [256*1024]
    float* out          = (float*)d_out;          // [512*256]

    dendritic_kernel<<<1024, 128>>>(spikes, W, out);
}